// round 1
// baseline (speedup 1.0000x reference)
#include <cuda_runtime.h>
#include <math.h>

#define B_   64
#define T_   20
#define N_   100
#define F_   64
#define H_   256
#define BT_  (B_*T_)        // 1280
#define BTN_ (B_*T_*N_)     // 128000
#define LN_EPS 1e-5f

// ---------------- scratch (static device globals; no allocation) ----------
__device__ float g_buf0[BTN_*H_];
__device__ float g_buf1[BTN_*H_];
__device__ float g_q[BTN_*H_];
__device__ float g_k[BTN_*H_];
__device__ float g_v[BTN_*H_];

// ---------------- GCN message passing: out[bt,n,f] = sum_m adj[n,m] h[bt,m,f]
// grid: (BT, F/64), block (16,16). smem: adj[100][101] + h tile [100][64].
__global__ void __launch_bounds__(256) msg_kernel(
    const float* __restrict__ h, const float* __restrict__ adj,
    float* __restrict__ out, int F) {
    extern __shared__ float sm[];
    float* adj_s = sm;              // [100][101] padded
    float* h_s   = sm + N_*101;     // [100][64]

    const int tid = threadIdx.y * 16 + threadIdx.x;
    const int bt  = blockIdx.x;
    const int f0  = blockIdx.y * 64;

    for (int idx = tid; idx < N_*N_; idx += 256) {
        int n = idx / N_, m = idx - n * N_;
        adj_s[n*101 + m] = adj[idx];
    }
    const float* hp = h + (size_t)bt * N_ * F + f0;
    for (int idx = tid; idx < N_*16; idx += 256) {
        int m = idx >> 4, c = idx & 15;
        ((float4*)(h_s + m*64))[c] = ((const float4*)(hp + (size_t)m * F))[c];
    }
    __syncthreads();

    const int tx = threadIdx.x, ty = threadIdx.y;
    float4 acc[7];
#pragma unroll
    for (int i = 0; i < 7; i++) acc[i] = make_float4(0.f, 0.f, 0.f, 0.f);

    for (int m = 0; m < N_; m++) {
        float4 hv = ((const float4*)(h_s + m*64))[tx];
#pragma unroll
        for (int i = 0; i < 7; i++) {
            int n = ty + 16*i;
            float a = (n < N_) ? adj_s[n*101 + m] : 0.f;
            acc[i].x = fmaf(a, hv.x, acc[i].x);
            acc[i].y = fmaf(a, hv.y, acc[i].y);
            acc[i].z = fmaf(a, hv.z, acc[i].z);
            acc[i].w = fmaf(a, hv.w, acc[i].w);
        }
    }
#pragma unroll
    for (int i = 0; i < 7; i++) {
        int n = ty + 16*i;
        if (n < N_)
            ((float4*)(out + ((size_t)bt * N_ + n) * F + f0))[tx] = acc[i];
    }
}

// ---------------- SGEMM: C[M,Nn] = A[M,K] @ B[K,Nn] + bias (+relu)(+res)
// 128x128 tile, K-step 8, 256 threads, 8x8 per thread.
template<bool RELU, bool RES>
__global__ void __launch_bounds__(256) sgemm_kernel(
    const float* __restrict__ A, const float* __restrict__ Bm,
    const float* __restrict__ bias, const float* __restrict__ res,
    float* __restrict__ C, int M, int Nn, int K) {
    __shared__ __align__(16) float As[8][132];
    __shared__ __align__(16) float Bs[8][128];

    const int tid = threadIdx.x;
    const int bx = blockIdx.x, by = blockIdx.y;
    const int arow = tid >> 1;
    const int acol = (tid & 1) << 2;
    const int brow = tid >> 5;
    const int bcol = (tid & 31) << 2;
    const int tx = tid & 15, ty = tid >> 4;

    const float* Ap = A + ((size_t)by * 128 + arow) * K + acol;
    const float* Bp = Bm + (size_t)brow * Nn + (size_t)bx * 128 + bcol;

    float acc[8][8];
#pragma unroll
    for (int i = 0; i < 8; i++)
#pragma unroll
        for (int j = 0; j < 8; j++) acc[i][j] = 0.f;

    for (int k0 = 0; k0 < K; k0 += 8) {
        float4 av = *(const float4*)(Ap + k0);
        float4 bv = *(const float4*)(Bp + (size_t)k0 * Nn);
        As[acol+0][arow] = av.x;
        As[acol+1][arow] = av.y;
        As[acol+2][arow] = av.z;
        As[acol+3][arow] = av.w;
        *(float4*)&Bs[brow][bcol] = bv;
        __syncthreads();
#pragma unroll
        for (int kk = 0; kk < 8; kk++) {
            float a[8], b[8];
            *(float4*)(a)   = *(const float4*)&As[kk][ty*8];
            *(float4*)(a+4) = *(const float4*)&As[kk][ty*8+4];
            *(float4*)(b)   = *(const float4*)&Bs[kk][tx*8];
            *(float4*)(b+4) = *(const float4*)&Bs[kk][tx*8+4];
#pragma unroll
            for (int i = 0; i < 8; i++)
#pragma unroll
                for (int j = 0; j < 8; j++)
                    acc[i][j] = fmaf(a[i], b[j], acc[i][j]);
        }
        __syncthreads();
    }

    const int crow0 = by * 128 + ty * 8;
    const int ccol0 = bx * 128 + tx * 8;
#pragma unroll
    for (int i = 0; i < 8; i++) {
        size_t roff = (size_t)(crow0 + i) * Nn + ccol0;
#pragma unroll
        for (int j = 0; j < 8; j += 4) {
            float4 o;
            o.x = acc[i][j+0] + bias[ccol0 + j + 0];
            o.y = acc[i][j+1] + bias[ccol0 + j + 1];
            o.z = acc[i][j+2] + bias[ccol0 + j + 2];
            o.w = acc[i][j+3] + bias[ccol0 + j + 3];
            if (RELU) {
                o.x = fmaxf(o.x, 0.f); o.y = fmaxf(o.y, 0.f);
                o.z = fmaxf(o.z, 0.f); o.w = fmaxf(o.w, 0.f);
            }
            if (RES) {
                float4 r = *(const float4*)(res + roff + j);
                o.x += r.x; o.y += r.y; o.z += r.z; o.w += r.w;
            }
            *(float4*)(C + roff + j) = o;
        }
    }
}

// ---------------- Temporal attention per (b,n): softmax(QK^T/16) V --------
// grid: B*N blocks, 256 threads. K,V tiles (20x256) + probs in smem.
__global__ void __launch_bounds__(256) attn_kernel(
    const float* __restrict__ q, const float* __restrict__ k,
    const float* __restrict__ v, float* __restrict__ out) {
    __shared__ __align__(16) float k_s[T_][H_];
    __shared__ __align__(16) float v_s[T_][H_];
    __shared__ float s_s[T_][T_];

    const int bn = blockIdx.x;
    const int b = bn / N_, n = bn - b * N_;
    const size_t base = ((size_t)b * T_ * N_ + n) * H_;   // (b, t=0, n, 0)
    const size_t tstride = (size_t)N_ * H_;
    const int tid = threadIdx.x;

    for (int idx = tid; idx < T_ * (H_/4); idx += 256) {
        int t = idx / (H_/4), hc = idx - t * (H_/4);
        ((float4*)k_s[t])[hc] = ((const float4*)(k + base + t * tstride))[hc];
        ((float4*)v_s[t])[hc] = ((const float4*)(v + base + t * tstride))[hc];
    }
    __syncthreads();

    for (int p = tid; p < T_*T_; p += 256) {
        int t = p / T_, s = p - t * T_;
        const float4* qp = (const float4*)(q + base + t * tstride);
        float acc = 0.f;
#pragma unroll 8
        for (int hc = 0; hc < H_/4; hc++) {
            float4 qv = qp[hc];
            float4 kv = ((const float4*)k_s[s])[hc];
            acc = fmaf(qv.x, kv.x, acc);
            acc = fmaf(qv.y, kv.y, acc);
            acc = fmaf(qv.z, kv.z, acc);
            acc = fmaf(qv.w, kv.w, acc);
        }
        s_s[t][s] = acc * 0.0625f;   // 1/sqrt(256)
    }
    __syncthreads();

    if (tid < T_) {
        float mx = -1e30f;
#pragma unroll
        for (int s = 0; s < T_; s++) mx = fmaxf(mx, s_s[tid][s]);
        float sum = 0.f;
#pragma unroll
        for (int s = 0; s < T_; s++) {
            float e = __expf(s_s[tid][s] - mx);
            s_s[tid][s] = e;
            sum += e;
        }
        float inv = 1.f / sum;
#pragma unroll
        for (int s = 0; s < T_; s++) s_s[tid][s] *= inv;
    }
    __syncthreads();

    for (int idx = tid; idx < T_ * (H_/4); idx += 256) {
        int t = idx / (H_/4), hc = idx - t * (H_/4);
        float4 acc = make_float4(0.f, 0.f, 0.f, 0.f);
#pragma unroll
        for (int s = 0; s < T_; s++) {
            float p = s_s[t][s];
            float4 vv = ((const float4*)v_s[s])[hc];
            acc.x = fmaf(p, vv.x, acc.x);
            acc.y = fmaf(p, vv.y, acc.y);
            acc.z = fmaf(p, vv.z, acc.z);
            acc.w = fmaf(p, vv.w, acc.w);
        }
        ((float4*)(out + base + t * tstride))[hc] = acc;
    }
}

// ---------------- LayerNorm over H=256, one warp per row ------------------
__inline__ __device__ float warp_sum(float val) {
#pragma unroll
    for (int o = 16; o; o >>= 1) val += __shfl_xor_sync(0xffffffffu, val, o);
    return val;
}

__global__ void __launch_bounds__(256) ln_kernel(
    const float* __restrict__ a, const float* __restrict__ gamma,
    const float* __restrict__ beta, float* __restrict__ out) {
    const int row  = blockIdx.x * 8 + (threadIdx.x >> 5);
    const int lane = threadIdx.x & 31;
    const float4* ap = (const float4*)(a + (size_t)row * H_);
    float4 v0 = ap[lane];
    float4 v1 = ap[lane + 32];

    float s = v0.x + v0.y + v0.z + v0.w + v1.x + v1.y + v1.z + v1.w;
    s = warp_sum(s);
    float mean = s * (1.f / H_);

    float d, sq = 0.f;
    d = v0.x - mean; sq = fmaf(d, d, sq);
    d = v0.y - mean; sq = fmaf(d, d, sq);
    d = v0.z - mean; sq = fmaf(d, d, sq);
    d = v0.w - mean; sq = fmaf(d, d, sq);
    d = v1.x - mean; sq = fmaf(d, d, sq);
    d = v1.y - mean; sq = fmaf(d, d, sq);
    d = v1.z - mean; sq = fmaf(d, d, sq);
    d = v1.w - mean; sq = fmaf(d, d, sq);
    sq = warp_sum(sq);
    float rstd = rsqrtf(sq * (1.f / H_) + LN_EPS);

    float4 g0 = ((const float4*)gamma)[lane];
    float4 g1 = ((const float4*)gamma)[lane + 32];
    float4 be0 = ((const float4*)beta)[lane];
    float4 be1 = ((const float4*)beta)[lane + 32];

    float4 o0, o1;
    o0.x = (v0.x - mean) * rstd * g0.x + be0.x;
    o0.y = (v0.y - mean) * rstd * g0.y + be0.y;
    o0.z = (v0.z - mean) * rstd * g0.z + be0.z;
    o0.w = (v0.w - mean) * rstd * g0.w + be0.w;
    o1.x = (v1.x - mean) * rstd * g1.x + be1.x;
    o1.y = (v1.y - mean) * rstd * g1.y + be1.y;
    o1.z = (v1.z - mean) * rstd * g1.z + be1.z;
    o1.w = (v1.w - mean) * rstd * g1.w + be1.w;

    float4* op = (float4*)(out + (size_t)row * H_);
    op[lane] = o0;
    op[lane + 32] = o1;
}

// ---------------- host launcher -------------------------------------------
extern "C" void kernel_launch(void* const* d_in, const int* in_sizes, int n_in,
                              void* d_out, int out_size) {
    const float* x     = (const float*)d_in[0];
    const float* adj   = (const float*)d_in[1];
    const float* W0    = (const float*)d_in[2];
    const float* b0    = (const float*)d_in[3];
    const float* W1    = (const float*)d_in[4];
    const float* b1    = (const float*)d_in[5];
    const float* W2    = (const float*)d_in[6];
    const float* b2    = (const float*)d_in[7];
    const float* Wq    = (const float*)d_in[8];
    const float* bq    = (const float*)d_in[9];
    const float* Wk    = (const float*)d_in[10];
    const float* bk    = (const float*)d_in[11];
    const float* Wv    = (const float*)d_in[12];
    const float* bv    = (const float*)d_in[13];
    const float* Wp    = (const float*)d_in[14];
    const float* bp    = (const float*)d_in[15];
    const float* gamma = (const float*)d_in[16];
    const float* beta  = (const float*)d_in[17];
    float* outp = (float*)d_out;

    float *buf0, *buf1, *q, *k, *v;
    cudaGetSymbolAddress((void**)&buf0, g_buf0);
    cudaGetSymbolAddress((void**)&buf1, g_buf1);
    cudaGetSymbolAddress((void**)&q,    g_q);
    cudaGetSymbolAddress((void**)&k,    g_k);
    cudaGetSymbolAddress((void**)&v,    g_v);

    const size_t msg_smem = (size_t)(N_*101 + N_*64) * sizeof(float); // 66000B
    cudaFuncSetAttribute(msg_kernel, cudaFuncAttributeMaxDynamicSharedMemorySize,
                         (int)msg_smem);

    dim3 msgBlk(16, 16);
    dim3 gemmGrid(2, 1000);   // N=256/128, M=128000/128

    // GCN layer 0: F=64 -> H, relu, no residual
    msg_kernel<<<dim3(BT_, 1), msgBlk, msg_smem>>>(x, adj, buf1, F_);
    sgemm_kernel<true, false><<<gemmGrid, 256>>>(buf1, W0, b0, nullptr, buf0,
                                                 BTN_, H_, F_);
    // GCN layer 1: relu + residual(buf0) -> q (temp)
    msg_kernel<<<dim3(BT_, 4), msgBlk, msg_smem>>>(buf0, adj, buf1, H_);
    sgemm_kernel<true, true><<<gemmGrid, 256>>>(buf1, W1, b1, buf0, q,
                                                BTN_, H_, H_);
    // GCN layer 2: relu + residual(q) -> buf0 (= h)
    msg_kernel<<<dim3(BT_, 4), msgBlk, msg_smem>>>(q, adj, buf1, H_);
    sgemm_kernel<true, true><<<gemmGrid, 256>>>(buf1, W2, b2, q, buf0,
                                                BTN_, H_, H_);
    // QKV projections
    sgemm_kernel<false, false><<<gemmGrid, 256>>>(buf0, Wq, bq, nullptr, q,
                                                  BTN_, H_, H_);
    sgemm_kernel<false, false><<<gemmGrid, 256>>>(buf0, Wk, bk, nullptr, k,
                                                  BTN_, H_, H_);
    sgemm_kernel<false, false><<<gemmGrid, 256>>>(buf0, Wv, bv, nullptr, v,
                                                  BTN_, H_, H_);
    // temporal attention -> buf1
    attn_kernel<<<B_*N_, 256>>>(q, k, v, buf1);
    // output projection -> q
    sgemm_kernel<false, false><<<gemmGrid, 256>>>(buf1, Wp, bp, nullptr, q,
                                                  BTN_, H_, H_);
    // layernorm -> d_out
    ln_kernel<<<BTN_/8, 256>>>(q, gamma, beta, outp);
}

// round 2
// speedup vs baseline: 1.1615x; 1.1615x over previous
#include <cuda_runtime.h>
#include <math.h>

#define B_   64
#define T_   20
#define N_   100
#define F_   64
#define H_   256
#define BT_  (B_*T_)        // 1280
#define BTN_ (B_*T_*N_)     // 128000
#define NP_  128            // padded node count
#define LN_EPS 1e-5f

// ---------------- scratch (static device globals; no allocation) ----------
// node-major layout: row = n*BT + bt, padded to 128 n-rows where used as B
__device__ float g_x   [NP_*BT_*F_];     // x transposed, rows >=100 stay zero
__device__ float g_m   [N_*BT_*H_];      // msg output / attn output scratch
__device__ float g_h0  [NP_*BT_*H_];     // h ping (padded rows stay zero)
__device__ float g_h1  [NP_*BT_*H_];     // h pong (padded rows stay zero)
__device__ float g_qkv [BTN_*3*H_];      // packed q|k|v, row stride 768
__device__ float g_adjp[NP_*NP_];        // zero-padded adjacency
__device__ float g_wqkv[H_*3*H_];
__device__ float g_bqkv[3*H_];

// ---------------- prep kernels --------------------------------------------
__global__ void adj_prep(const float* __restrict__ adj, float* __restrict__ adjp) {
    int i = blockIdx.x * 256 + threadIdx.x;       // 16384
    int n = i >> 7, m = i & 127;
    adjp[i] = (n < N_ && m < N_) ? adj[n * N_ + m] : 0.f;
}

__global__ void qkv_prep(const float* __restrict__ Wq, const float* __restrict__ Wk,
                         const float* __restrict__ Wv, const float* __restrict__ bq,
                         const float* __restrict__ bk, const float* __restrict__ bv,
                         float* __restrict__ wqkv, float* __restrict__ bqkv) {
    int i = blockIdx.x * 256 + threadIdx.x;       // 196608
    int r = i / (3*H_), c = i % (3*H_);
    int w = c >> 8, cc = c & 255;
    const float* W = (w == 0) ? Wq : (w == 1) ? Wk : Wv;
    wqkv[i] = W[r * H_ + cc];
    if (i < 3*H_) {
        const float* bb = (i < H_) ? bq : (i < 2*H_) ? bk : bv;
        bqkv[i] = bb[i & 255];
    }
}

// x[b,t,n,f] -> g_x[(n*BT + bt)*F + f]
__global__ void xpose_kernel(const float* __restrict__ x, float* __restrict__ xT) {
    int idx = blockIdx.x * 256 + threadIdx.x;     // BTN*16 float4s
    if (idx >= BTN_ * (F_/4)) return;
    int c   = idx & 15;
    int row = idx >> 4;            // bt*100 + n
    int n   = row % N_;
    int bt  = row / N_;
    ((float4*)xT)[(n * BT_ + bt) * (F_/4) + c] = ((const float4*)x)[idx];
}

// ---------------- double-buffered SGEMM -----------------------------------
// C[M,Nn] = A[M,K] @ B[K,Nn] (+bias)(relu)(+res). 128x128 tile, Kstep 8.
// MG: store-guard rows >= Mvalid (used for padded adj GEMM, M=128).
template<bool BIAS, bool RELU, bool RES, bool MG>
__global__ void __launch_bounds__(256) sgemm_kernel(
    const float* __restrict__ A, const float* __restrict__ Bm,
    const float* __restrict__ bias, const float* __restrict__ res,
    float* __restrict__ C, int M, int Nn, int K, int Mvalid) {
    __shared__ __align__(16) float As[2][8][132];
    __shared__ __align__(16) float Bs[2][8][128];

    const int tid = threadIdx.x;
    const int bx = blockIdx.x, by = blockIdx.y;
    const int arow = tid >> 1, acol = (tid & 1) << 2;
    const int brow = tid >> 5, bcol = (tid & 31) << 2;
    const int tx = tid & 15, ty = tid >> 4;

    const float* Ap = A + ((size_t)by * 128 + arow) * K + acol;
    const float* Bp = Bm + (size_t)brow * Nn + (size_t)bx * 128 + bcol;

    float acc[8][8];
#pragma unroll
    for (int i = 0; i < 8; i++)
#pragma unroll
        for (int j = 0; j < 8; j++) acc[i][j] = 0.f;

    // prologue: tile 0 -> buf 0
    {
        float4 av = *(const float4*)(Ap);
        float4 bv = *(const float4*)(Bp);
        As[0][acol+0][arow] = av.x;
        As[0][acol+1][arow] = av.y;
        As[0][acol+2][arow] = av.z;
        As[0][acol+3][arow] = av.w;
        *(float4*)&Bs[0][brow][bcol] = bv;
    }
    __syncthreads();

    int buf = 0;
    for (int k0 = 8; k0 <= K; k0 += 8) {
        const bool more = (k0 < K);
        float4 av, bv;
        if (more) {
            av = *(const float4*)(Ap + k0);
            bv = *(const float4*)(Bp + (size_t)k0 * Nn);
        }
        const float (*Asb)[132] = As[buf];
        const float (*Bsb)[128] = Bs[buf];
#pragma unroll
        for (int kk = 0; kk < 8; kk++) {
            float a[8], b[8];
            *(float4*)(a)   = *(const float4*)&Asb[kk][ty*8];
            *(float4*)(a+4) = *(const float4*)&Asb[kk][ty*8+4];
            *(float4*)(b)   = *(const float4*)&Bsb[kk][tx*8];
            *(float4*)(b+4) = *(const float4*)&Bsb[kk][tx*8+4];
#pragma unroll
            for (int i = 0; i < 8; i++)
#pragma unroll
                for (int j = 0; j < 8; j++)
                    acc[i][j] = fmaf(a[i], b[j], acc[i][j]);
        }
        if (more) {
            const int nb = buf ^ 1;
            As[nb][acol+0][arow] = av.x;
            As[nb][acol+1][arow] = av.y;
            As[nb][acol+2][arow] = av.z;
            As[nb][acol+3][arow] = av.w;
            *(float4*)&Bs[nb][brow][bcol] = bv;
            __syncthreads();
            buf = nb;
        }
    }

    const int crow0 = by * 128 + ty * 8;
    const int ccol0 = bx * 128 + tx * 8;
#pragma unroll
    for (int i = 0; i < 8; i++) {
        if (MG && (crow0 + i) >= Mvalid) continue;
        size_t roff = (size_t)(crow0 + i) * Nn + ccol0;
#pragma unroll
        for (int j = 0; j < 8; j += 4) {
            float4 o;
            o.x = acc[i][j+0]; o.y = acc[i][j+1];
            o.z = acc[i][j+2]; o.w = acc[i][j+3];
            if (BIAS) {
                o.x += bias[ccol0 + j + 0];
                o.y += bias[ccol0 + j + 1];
                o.z += bias[ccol0 + j + 2];
                o.w += bias[ccol0 + j + 3];
            }
            if (RELU) {
                o.x = fmaxf(o.x, 0.f); o.y = fmaxf(o.y, 0.f);
                o.z = fmaxf(o.z, 0.f); o.w = fmaxf(o.w, 0.f);
            }
            if (RES) {
                float4 r = *(const float4*)(res + roff + j);
                o.x += r.x; o.y += r.y; o.z += r.z; o.w += r.w;
            }
            *(float4*)(C + roff + j) = o;
        }
    }
}

// ---------------- Temporal attention (packed qkv, node-major) -------------
// per (n,b): 20 consecutive rows of g_qkv (row = n*BT + b*T + t, stride 768)
#define HP_ 260   // padded row stride in smem floats
__global__ void __launch_bounds__(256) attn_kernel(
    const float* __restrict__ qkv, float* __restrict__ out) {
    extern __shared__ float sm[];
    float* q_s = sm;               // [20][260]
    float* k_s = sm + T_*HP_;
    float* v_s = sm + 2*T_*HP_;
    float* s_s = sm + 3*T_*HP_;    // [20][20]

    const int bn = blockIdx.x;     // n*64 + b
    const int n = bn >> 6, b = bn & 63;
    const size_t row0 = (size_t)n * BT_ + (size_t)b * T_;
    const int tid = threadIdx.x;

    // load 20 rows x 768 floats (contiguous block)
    for (int idx = tid; idx < T_ * 192; idx += 256) {
        int t = idx / 192, c = idx % 192;      // c: float4 over 768
        float4 val = ((const float4*)(qkv + (row0 + t) * (3*H_)))[c];
        int which = c >> 6, h4 = c & 63;
        float* dst = (which == 0 ? q_s : which == 1 ? k_s : v_s) + t * HP_ + h4 * 4;
        *(float4*)dst = val;
    }
    __syncthreads();

    // scores
    for (int p = tid; p < T_*T_; p += 256) {
        int t = p / T_, s = p - t * T_;
        float ax = 0.f, ay = 0.f, az = 0.f, aw = 0.f;
        const float4* qp = (const float4*)(q_s + t * HP_);
        const float4* kp = (const float4*)(k_s + s * HP_);
#pragma unroll 8
        for (int hc = 0; hc < H_/4; hc++) {
            float4 qv = qp[hc];
            float4 kv = kp[hc];
            ax = fmaf(qv.x, kv.x, ax);
            ay = fmaf(qv.y, kv.y, ay);
            az = fmaf(qv.z, kv.z, az);
            aw = fmaf(qv.w, kv.w, aw);
        }
        s_s[t*T_ + s] = (ax + ay + az + aw) * 0.0625f;   // 1/sqrt(256)
    }
    __syncthreads();

    if (tid < T_) {
        float mx = -1e30f;
#pragma unroll
        for (int s = 0; s < T_; s++) mx = fmaxf(mx, s_s[tid*T_+s]);
        float sum = 0.f;
#pragma unroll
        for (int s = 0; s < T_; s++) {
            float e = __expf(s_s[tid*T_+s] - mx);
            s_s[tid*T_+s] = e;
            sum += e;
        }
        float inv = 1.f / sum;
#pragma unroll
        for (int s = 0; s < T_; s++) s_s[tid*T_+s] *= inv;
    }
    __syncthreads();

    // out[row0+t][h] = sum_s p[t][s] * v[s][h]   (out row stride 256)
    for (int idx = tid; idx < T_ * (H_/4); idx += 256) {
        int t = idx >> 6, hc = idx & 63;
        float4 acc = make_float4(0.f, 0.f, 0.f, 0.f);
#pragma unroll
        for (int s = 0; s < T_; s++) {
            float p = s_s[t*T_ + s];
            float4 vv = ((const float4*)(v_s + s * HP_))[hc];
            acc.x = fmaf(p, vv.x, acc.x);
            acc.y = fmaf(p, vv.y, acc.y);
            acc.z = fmaf(p, vv.z, acc.z);
            acc.w = fmaf(p, vv.w, acc.w);
        }
        ((float4*)(out + (row0 + t) * H_))[hc] = acc;
    }
}

// ---------------- LayerNorm + scatter back to [b,t,n,h] -------------------
__inline__ __device__ float warp_sum(float val) {
#pragma unroll
    for (int o = 16; o; o >>= 1) val += __shfl_xor_sync(0xffffffffu, val, o);
    return val;
}

__global__ void __launch_bounds__(256) ln_kernel(
    const float* __restrict__ a, const float* __restrict__ gamma,
    const float* __restrict__ beta, float* __restrict__ out) {
    const int row  = blockIdx.x * 8 + (threadIdx.x >> 5);   // n*BT + bt
    const int lane = threadIdx.x & 31;
    const float4* ap = (const float4*)(a + (size_t)row * H_);
    float4 v0 = ap[lane];
    float4 v1 = ap[lane + 32];

    float s = v0.x + v0.y + v0.z + v0.w + v1.x + v1.y + v1.z + v1.w;
    s = warp_sum(s);
    float mean = s * (1.f / H_);

    float d, sq = 0.f;
    d = v0.x - mean; sq = fmaf(d, d, sq);
    d = v0.y - mean; sq = fmaf(d, d, sq);
    d = v0.z - mean; sq = fmaf(d, d, sq);
    d = v0.w - mean; sq = fmaf(d, d, sq);
    d = v1.x - mean; sq = fmaf(d, d, sq);
    d = v1.y - mean; sq = fmaf(d, d, sq);
    d = v1.z - mean; sq = fmaf(d, d, sq);
    d = v1.w - mean; sq = fmaf(d, d, sq);
    sq = warp_sum(sq);
    float rstd = rsqrtf(sq * (1.f / H_) + LN_EPS);

    float4 g0 = ((const float4*)gamma)[lane];
    float4 g1 = ((const float4*)gamma)[lane + 32];
    float4 be0 = ((const float4*)beta)[lane];
    float4 be1 = ((const float4*)beta)[lane + 32];

    float4 o0, o1;
    o0.x = (v0.x - mean) * rstd * g0.x + be0.x;
    o0.y = (v0.y - mean) * rstd * g0.y + be0.y;
    o0.z = (v0.z - mean) * rstd * g0.z + be0.z;
    o0.w = (v0.w - mean) * rstd * g0.w + be0.w;
    o1.x = (v1.x - mean) * rstd * g1.x + be1.x;
    o1.y = (v1.y - mean) * rstd * g1.y + be1.y;
    o1.z = (v1.z - mean) * rstd * g1.z + be1.z;
    o1.w = (v1.w - mean) * rstd * g1.w + be1.w;

    const int n = row / BT_, bt = row % BT_;
    float4* op = (float4*)(out + ((size_t)bt * N_ + n) * H_);
    op[lane] = o0;
    op[lane + 32] = o1;
}

// ---------------- host launcher -------------------------------------------
extern "C" void kernel_launch(void* const* d_in, const int* in_sizes, int n_in,
                              void* d_out, int out_size) {
    const float* x     = (const float*)d_in[0];
    const float* adj   = (const float*)d_in[1];
    const float* W0    = (const float*)d_in[2];
    const float* b0    = (const float*)d_in[3];
    const float* W1    = (const float*)d_in[4];
    const float* b1    = (const float*)d_in[5];
    const float* W2    = (const float*)d_in[6];
    const float* b2    = (const float*)d_in[7];
    const float* Wq    = (const float*)d_in[8];
    const float* bq    = (const float*)d_in[9];
    const float* Wk    = (const float*)d_in[10];
    const float* bk    = (const float*)d_in[11];
    const float* Wv    = (const float*)d_in[12];
    const float* bv    = (const float*)d_in[13];
    const float* Wp    = (const float*)d_in[14];
    const float* bp    = (const float*)d_in[15];
    const float* gamma = (const float*)d_in[16];
    const float* beta  = (const float*)d_in[17];
    float* outp = (float*)d_out;

    float *xT, *m, *h0, *h1, *qkv, *adjp, *wqkv, *bqkv;
    cudaGetSymbolAddress((void**)&xT,   g_x);
    cudaGetSymbolAddress((void**)&m,    g_m);
    cudaGetSymbolAddress((void**)&h0,   g_h0);
    cudaGetSymbolAddress((void**)&h1,   g_h1);
    cudaGetSymbolAddress((void**)&qkv,  g_qkv);
    cudaGetSymbolAddress((void**)&adjp, g_adjp);
    cudaGetSymbolAddress((void**)&wqkv, g_wqkv);
    cudaGetSymbolAddress((void**)&bqkv, g_bqkv);

    const int attn_smem = (3*T_*HP_ + T_*T_) * sizeof(float);  // 64000 B
    cudaFuncSetAttribute(attn_kernel, cudaFuncAttributeMaxDynamicSharedMemorySize,
                         attn_smem);

    // prep
    adj_prep<<<64, 256>>>(adj, adjp);
    qkv_prep<<<768, 256>>>(Wq, Wk, Wv, bq, bk, bv, wqkv, bqkv);
    xpose_kernel<<<(BTN_*(F_/4) + 255)/256, 256>>>(x, xT);

    // GCN layer 0: msg (K=128 padded, Nn=BT*F) then F->H GEMM + relu
    sgemm_kernel<false,false,false,true><<<dim3(BT_*F_/128, 1), 256>>>(
        adjp, xT, nullptr, nullptr, m, NP_, BT_*F_, NP_, N_);
    sgemm_kernel<true,true,false,false><<<dim3(2, 1000), 256>>>(
        m, W0, b0, nullptr, h0, BTN_, H_, F_, BTN_);

    // GCN layer 1
    sgemm_kernel<false,false,false,true><<<dim3(BT_*H_/128, 1), 256>>>(
        adjp, h0, nullptr, nullptr, m, NP_, BT_*H_, NP_, N_);
    sgemm_kernel<true,true,true,false><<<dim3(2, 1000), 256>>>(
        m, W1, b1, h0, h1, BTN_, H_, H_, BTN_);

    // GCN layer 2
    sgemm_kernel<false,false,false,true><<<dim3(BT_*H_/128, 1), 256>>>(
        adjp, h1, nullptr, nullptr, m, NP_, BT_*H_, NP_, N_);
    sgemm_kernel<true,true,true,false><<<dim3(2, 1000), 256>>>(
        m, W2, b2, h1, h0, BTN_, H_, H_, BTN_);

    // fused QKV projection: [128000 x 256] @ [256 x 768]
    sgemm_kernel<true,false,false,false><<<dim3(6, 1000), 256>>>(
        h0, wqkv, bqkv, nullptr, qkv, BTN_, 3*H_, H_, BTN_);

    // temporal attention -> m
    attn_kernel<<<N_*B_, 256, attn_smem>>>(qkv, m);

    // output projection -> h1
    sgemm_kernel<true,false,false,false><<<dim3(2, 1000), 256>>>(
        m, Wp, bp, nullptr, h1, BTN_, H_, H_, BTN_);

    // layernorm + scatter to [b,t,n,h]
    ln_kernel<<<BTN_/8, 256>>>(h1, gamma, beta, outp);
}

// round 5
// speedup vs baseline: 1.1803x; 1.0161x over previous
#include <cuda_runtime.h>
#include <math.h>
#include <stdint.h>

#define B_   64
#define T_   20
#define N_   100
#define F_   64
#define H_   256
#define BT_  (B_*T_)        // 1280
#define BTN_ (B_*T_*N_)     // 128000
#define NP_  128            // padded node count
#define LN_EPS 1e-5f

typedef unsigned long long u64;

// ---------------- f32x2 packed-math helpers (sm_103a) ----------------------
__device__ __forceinline__ u64 fma2(u64 a, u64 b, u64 c) {
    u64 d;
    asm("fma.rn.f32x2 %0, %1, %2, %3;" : "=l"(d) : "l"(a), "l"(b), "l"(c));
    return d;
}
__device__ __forceinline__ u64 dup2(float x) {
    u64 d;
    asm("mov.b64 %0, {%1, %1};" : "=l"(d) : "f"(x));
    return d;
}
__device__ __forceinline__ float2 unpack2(u64 v) {
    float2 r;
    asm("mov.b64 {%0, %1}, %2;" : "=f"(r.x), "=f"(r.y) : "l"(v));
    return r;
}

// ---------------- scratch (static device globals; no allocation) ----------
__device__ float g_x   [NP_*BT_*F_];     // x transposed, node-major
__device__ float g_m   [N_*BT_*H_];      // msg / attn scratch
__device__ float g_h0  [NP_*BT_*H_];
__device__ float g_h1  [NP_*BT_*H_];
__device__ float g_qkv [BTN_*3*H_];      // packed q|k|v, row stride 768
__device__ float g_adjp[NP_*NP_];
__device__ float g_wqkv[H_*3*H_];
__device__ float g_bqkv[3*H_];

// ---------------- prep kernels --------------------------------------------
__global__ void adj_prep(const float* __restrict__ adj, float* __restrict__ adjp) {
    int i = blockIdx.x * 256 + threadIdx.x;       // 16384
    int n = i >> 7, m = i & 127;
    adjp[i] = (n < N_ && m < N_) ? adj[n * N_ + m] : 0.f;
}

__global__ void qkv_prep(const float* __restrict__ Wq, const float* __restrict__ Wk,
                         const float* __restrict__ Wv, const float* __restrict__ bq,
                         const float* __restrict__ bk, const float* __restrict__ bv,
                         float* __restrict__ wqkv, float* __restrict__ bqkv) {
    int i = blockIdx.x * 256 + threadIdx.x;       // 196608
    int r = i / (3*H_), c = i % (3*H_);
    int w = c >> 8, cc = c & 255;
    const float* W = (w == 0) ? Wq : (w == 1) ? Wk : Wv;
    wqkv[i] = W[r * H_ + cc];
    if (i < 3*H_) {
        const float* bb = (i < H_) ? bq : (i < 2*H_) ? bk : bv;
        bqkv[i] = bb[i & 255];
    }
}

// x[b,t,n,f] -> g_x[(n*BT + bt)*F + f]
__global__ void xpose_kernel(const float* __restrict__ x, float* __restrict__ xT) {
    int idx = blockIdx.x * 256 + threadIdx.x;
    if (idx >= BTN_ * (F_/4)) return;
    int c   = idx & 15;
    int row = idx >> 4;            // bt*100 + n
    int n   = row % N_;
    int bt  = row / N_;
    ((float4*)xT)[(n * BT_ + bt) * (F_/4) + c] = ((const float4*)x)[idx];
}

// ---------------- double-buffered SGEMM with f32x2 core --------------------
// C[M,Nn] = A[M,K] @ B[K,Nn] (+bias)(relu)(+res). 128x128 tile, Kstep 8.
// MG: store-guard rows >= Mvalid (used for padded adj GEMM, M=128).
template<bool BIAS, bool RELU, bool RES, bool MG>
__global__ void __launch_bounds__(256) sgemm_kernel(
    const float* __restrict__ A, const float* __restrict__ Bm,
    const float* __restrict__ bias, const float* __restrict__ res,
    float* __restrict__ C, int M, int Nn, int K, int Mvalid) {
    __shared__ __align__(16) float As[2][8][132];
    __shared__ __align__(16) float Bs[2][8][128];

    const int tid = threadIdx.x;
    const int bx = blockIdx.x, by = blockIdx.y;
    const int arow = tid >> 1, acol = (tid & 1) << 2;
    const int brow = tid >> 5, bcol = (tid & 31) << 2;
    const int tx = tid & 15, ty = tid >> 4;

    const float* Ap = A + ((size_t)by * 128 + arow) * K + acol;
    const float* Bp = Bm + (size_t)brow * Nn + (size_t)bx * 128 + bcol;

    // packed accumulators: 8 rows x 4 column-pairs (cols tx*8 .. tx*8+7)
    u64 acc[8][4];
#pragma unroll
    for (int i = 0; i < 8; i++)
#pragma unroll
        for (int j = 0; j < 4; j++) acc[i][j] = 0ull;

    // prologue: tile 0 -> buf 0
    {
        float4 av = *(const float4*)(Ap);
        float4 bv = *(const float4*)(Bp);
        As[0][acol+0][arow] = av.x;
        As[0][acol+1][arow] = av.y;
        As[0][acol+2][arow] = av.z;
        As[0][acol+3][arow] = av.w;
        *(float4*)&Bs[0][brow][bcol] = bv;
    }
    __syncthreads();

    int buf = 0;
    for (int k0 = 8; k0 <= K; k0 += 8) {
        const bool more = (k0 < K);
        float4 av, bv;
        if (more) {
            av = *(const float4*)(Ap + k0);
            bv = *(const float4*)(Bp + (size_t)k0 * Nn);
        }
        const float (*Asb)[132] = As[buf];
        const float (*Bsb)[128] = Bs[buf];
#pragma unroll
        for (int kk = 0; kk < 8; kk++) {
            float a[8];
            *(float4*)(a)   = *(const float4*)&Asb[kk][ty*8];
            *(float4*)(a+4) = *(const float4*)&Asb[kk][ty*8+4];
            // B pairs: 8 consecutive cols = 4 u64 pairs, via two 16B LDS
            ulonglong2 bp0 = *(const ulonglong2*)&Bsb[kk][tx*8];
            ulonglong2 bp1 = *(const ulonglong2*)&Bsb[kk][tx*8+4];
            u64 b2[4] = { bp0.x, bp0.y, bp1.x, bp1.y };
#pragma unroll
            for (int i = 0; i < 8; i++) {
                u64 ad = dup2(a[i]);
#pragma unroll
                for (int j = 0; j < 4; j++)
                    acc[i][j] = fma2(ad, b2[j], acc[i][j]);
            }
        }
        if (more) {
            const int nb = buf ^ 1;
            As[nb][acol+0][arow] = av.x;
            As[nb][acol+1][arow] = av.y;
            As[nb][acol+2][arow] = av.z;
            As[nb][acol+3][arow] = av.w;
            *(float4*)&Bs[nb][brow][bcol] = bv;
            __syncthreads();
            buf = nb;
        }
    }

    const int crow0 = by * 128 + ty * 8;
    const int ccol0 = bx * 128 + tx * 8;
#pragma unroll
    for (int i = 0; i < 8; i++) {
        if (MG && (crow0 + i) >= Mvalid) continue;
        size_t roff = (size_t)(crow0 + i) * Nn + ccol0;
#pragma unroll
        for (int jh = 0; jh < 2; jh++) {       // two float4 stores per row
            float2 p0 = unpack2(acc[i][jh*2 + 0]);
            float2 p1 = unpack2(acc[i][jh*2 + 1]);
            int j = jh * 4;
            float4 o;
            o.x = p0.x; o.y = p0.y; o.z = p1.x; o.w = p1.y;
            if (BIAS) {
                o.x += bias[ccol0 + j + 0];
                o.y += bias[ccol0 + j + 1];
                o.z += bias[ccol0 + j + 2];
                o.w += bias[ccol0 + j + 3];
            }
            if (RELU) {
                o.x = fmaxf(o.x, 0.f); o.y = fmaxf(o.y, 0.f);
                o.z = fmaxf(o.z, 0.f); o.w = fmaxf(o.w, 0.f);
            }
            if (RES) {
                float4 r = *(const float4*)(res + roff + j);
                o.x += r.x; o.y += r.y; o.z += r.z; o.w += r.w;
            }
            *(float4*)(C + roff + j) = o;
        }
    }
}

// ---------------- Temporal attention (packed qkv, node-major) -------------
#define HP_ 260
__global__ void __launch_bounds__(256) attn_kernel(
    const float* __restrict__ qkv, float* __restrict__ out) {
    extern __shared__ float smf[];
    float* q_s = smf;
    float* k_s = smf + T_*HP_;
    float* v_s = smf + 2*T_*HP_;
    float* s_s = smf + 3*T_*HP_;

    const int bn = blockIdx.x;
    const int n = bn >> 6, b = bn & 63;
    const size_t row0 = (size_t)n * BT_ + (size_t)b * T_;
    const int tid = threadIdx.x;

    for (int idx = tid; idx < T_ * 192; idx += 256) {
        int t = idx / 192, c = idx % 192;
        float4 val = ((const float4*)(qkv + (row0 + t) * (3*H_)))[c];
        int which = c >> 6, h4 = c & 63;
        float* dst = (which == 0 ? q_s : which == 1 ? k_s : v_s) + t * HP_ + h4 * 4;
        *(float4*)dst = val;
    }
    __syncthreads();

    for (int p = tid; p < T_*T_; p += 256) {
        int t = p / T_, s = p - t * T_;
        float ax = 0.f, ay = 0.f, az = 0.f, aw = 0.f;
        const float4* qp = (const float4*)(q_s + t * HP_);
        const float4* kp = (const float4*)(k_s + s * HP_);
#pragma unroll 8
        for (int hc = 0; hc < H_/4; hc++) {
            float4 qv = qp[hc];
            float4 kv = kp[hc];
            ax = fmaf(qv.x, kv.x, ax);
            ay = fmaf(qv.y, kv.y, ay);
            az = fmaf(qv.z, kv.z, az);
            aw = fmaf(qv.w, kv.w, aw);
        }
        s_s[t*T_ + s] = (ax + ay + az + aw) * 0.0625f;
    }
    __syncthreads();

    if (tid < T_) {
        float mx = -1e30f;
#pragma unroll
        for (int s = 0; s < T_; s++) mx = fmaxf(mx, s_s[tid*T_+s]);
        float sum = 0.f;
#pragma unroll
        for (int s = 0; s < T_; s++) {
            float e = __expf(s_s[tid*T_+s] - mx);
            s_s[tid*T_+s] = e;
            sum += e;
        }
        float inv = 1.f / sum;
#pragma unroll
        for (int s = 0; s < T_; s++) s_s[tid*T_+s] *= inv;
    }
    __syncthreads();

    for (int idx = tid; idx < T_ * (H_/4); idx += 256) {
        int t = idx >> 6, hc = idx & 63;
        float4 acc = make_float4(0.f, 0.f, 0.f, 0.f);
#pragma unroll
        for (int s = 0; s < T_; s++) {
            float p = s_s[t*T_ + s];
            float4 vv = ((const float4*)(v_s + s * HP_))[hc];
            acc.x = fmaf(p, vv.x, acc.x);
            acc.y = fmaf(p, vv.y, acc.y);
            acc.z = fmaf(p, vv.z, acc.z);
            acc.w = fmaf(p, vv.w, acc.w);
        }
        ((float4*)(out + (row0 + t) * H_))[hc] = acc;
    }
}

// ---------------- LayerNorm + scatter back to [b,t,n,h] -------------------
__inline__ __device__ float warp_sum(float val) {
#pragma unroll
    for (int o = 16; o; o >>= 1) val += __shfl_xor_sync(0xffffffffu, val, o);
    return val;
}

__global__ void __launch_bounds__(256) ln_kernel(
    const float* __restrict__ a, const float* __restrict__ gamma,
    const float* __restrict__ beta, float* __restrict__ out) {
    const int row  = blockIdx.x * 8 + (threadIdx.x >> 5);   // n*BT + bt
    const int lane = threadIdx.x & 31;
    const float4* ap = (const float4*)(a + (size_t)row * H_);
    float4 v0 = ap[lane];
    float4 v1 = ap[lane + 32];

    float s = v0.x + v0.y + v0.z + v0.w + v1.x + v1.y + v1.z + v1.w;
    s = warp_sum(s);
    float mean = s * (1.f / H_);

    float d, sq = 0.f;
    d = v0.x - mean; sq = fmaf(d, d, sq);
    d = v0.y - mean; sq = fmaf(d, d, sq);
    d = v0.z - mean; sq = fmaf(d, d, sq);
    d = v0.w - mean; sq = fmaf(d, d, sq);
    d = v1.x - mean; sq = fmaf(d, d, sq);
    d = v1.y - mean; sq = fmaf(d, d, sq);
    d = v1.z - mean; sq = fmaf(d, d, sq);
    d = v1.w - mean; sq = fmaf(d, d, sq);
    sq = warp_sum(sq);
    float rstd = rsqrtf(sq * (1.f / H_) + LN_EPS);

    float4 g0 = ((const float4*)gamma)[lane];
    float4 g1 = ((const float4*)gamma)[lane + 32];
    float4 be0 = ((const float4*)beta)[lane];
    float4 be1 = ((const float4*)beta)[lane + 32];

    float4 o0, o1;
    o0.x = (v0.x - mean) * rstd * g0.x + be0.x;
    o0.y = (v0.y - mean) * rstd * g0.y + be0.y;
    o0.z = (v0.z - mean) * rstd * g0.z + be0.z;
    o0.w = (v0.w - mean) * rstd * g0.w + be0.w;
    o1.x = (v1.x - mean) * rstd * g1.x + be1.x;
    o1.y = (v1.y - mean) * rstd * g1.y + be1.y;
    o1.z = (v1.z - mean) * rstd * g1.z + be1.z;
    o1.w = (v1.w - mean) * rstd * g1.w + be1.w;

    const int n = row / BT_, bt = row % BT_;
    float4* op = (float4*)(out + ((size_t)bt * N_ + n) * H_);
    op[lane] = o0;
    op[lane + 32] = o1;
}

// ---------------- host launcher -------------------------------------------
extern "C" void kernel_launch(void* const* d_in, const int* in_sizes, int n_in,
                              void* d_out, int out_size) {
    const float* x     = (const float*)d_in[0];
    const float* adj   = (const float*)d_in[1];
    const float* W0    = (const float*)d_in[2];
    const float* b0    = (const float*)d_in[3];
    const float* W1    = (const float*)d_in[4];
    const float* b1    = (const float*)d_in[5];
    const float* W2    = (const float*)d_in[6];
    const float* b2    = (const float*)d_in[7];
    const float* Wq    = (const float*)d_in[8];
    const float* bq    = (const float*)d_in[9];
    const float* Wk    = (const float*)d_in[10];
    const float* bk    = (const float*)d_in[11];
    const float* Wv    = (const float*)d_in[12];
    const float* bv    = (const float*)d_in[13];
    const float* Wp    = (const float*)d_in[14];
    const float* bp    = (const float*)d_in[15];
    const float* gamma = (const float*)d_in[16];
    const float* beta  = (const float*)d_in[17];
    float* outp = (float*)d_out;

    float *xT, *m, *h0, *h1, *qkv, *adjp, *wqkv, *bqkv;
    cudaGetSymbolAddress((void**)&xT,   g_x);
    cudaGetSymbolAddress((void**)&m,    g_m);
    cudaGetSymbolAddress((void**)&h0,   g_h0);
    cudaGetSymbolAddress((void**)&h1,   g_h1);
    cudaGetSymbolAddress((void**)&qkv,  g_qkv);
    cudaGetSymbolAddress((void**)&adjp, g_adjp);
    cudaGetSymbolAddress((void**)&wqkv, g_wqkv);
    cudaGetSymbolAddress((void**)&bqkv, g_bqkv);

    const int attn_smem = (3*T_*HP_ + T_*T_) * sizeof(float);  // 64000 B
    cudaFuncSetAttribute(attn_kernel, cudaFuncAttributeMaxDynamicSharedMemorySize,
                         attn_smem);

    // prep
    adj_prep<<<64, 256>>>(adj, adjp);
    qkv_prep<<<768, 256>>>(Wq, Wk, Wv, bq, bk, bv, wqkv, bqkv);
    xpose_kernel<<<(BTN_*(F_/4) + 255)/256, 256>>>(x, xT);

    // GCN layer 0: msg (K=128 padded, Nn=BT*F) then F->H GEMM + relu
    sgemm_kernel<false,false,false,true><<<dim3(BT_*F_/128, 1), 256>>>(
        adjp, xT, nullptr, nullptr, m, NP_, BT_*F_, NP_, N_);
    sgemm_kernel<true,true,false,false><<<dim3(2, 1000), 256>>>(
        m, W0, b0, nullptr, h0, BTN_, H_, F_, BTN_);

    // GCN layer 1
    sgemm_kernel<false,false,false,true><<<dim3(BT_*H_/128, 1), 256>>>(
        adjp, h0, nullptr, nullptr, m, NP_, BT_*H_, NP_, N_);
    sgemm_kernel<true,true,true,false><<<dim3(2, 1000), 256>>>(
        m, W1, b1, h0, h1, BTN_, H_, H_, BTN_);

    // GCN layer 2
    sgemm_kernel<false,false,false,true><<<dim3(BT_*H_/128, 1), 256>>>(
        adjp, h1, nullptr, nullptr, m, NP_, BT_*H_, NP_, N_);
    sgemm_kernel<true,true,true,false><<<dim3(2, 1000), 256>>>(
        m, W2, b2, h1, h0, BTN_, H_, H_, BTN_);

    // fused QKV projection: [128000 x 256] @ [256 x 768]
    sgemm_kernel<true,false,false,false><<<dim3(6, 1000), 256>>>(
        h0, wqkv, bqkv, nullptr, qkv, BTN_, 3*H_, H_, BTN_);

    // temporal attention -> m
    attn_kernel<<<N_*B_, 256, attn_smem>>>(qkv, m);

    // output projection -> h1
    sgemm_kernel<true,false,false,false><<<dim3(2, 1000), 256>>>(
        m, Wp, bp, nullptr, h1, BTN_, H_, H_, BTN_);

    // layernorm + scatter to [b,t,n,h]
    ln_kernel<<<BTN_/8, 256>>>(h1, gamma, beta, outp);
}

// round 6
// speedup vs baseline: 1.4282x; 1.2101x over previous
#include <cuda_runtime.h>
#include <math.h>
#include <stdint.h>

#define B_   64
#define T_   20
#define N_   100
#define F_   64
#define H_   256
#define BT_  (B_*T_)        // 1280
#define BTN_ (B_*T_*N_)     // 128000
#define NP_  128            // padded node count
#define LN_EPS 1e-5f

typedef unsigned long long u64;

// ---------------- f32x2 packed-math helpers (sm_103a) ----------------------
__device__ __forceinline__ u64 fma2(u64 a, u64 b, u64 c) {
    u64 d;
    asm("fma.rn.f32x2 %0, %1, %2, %3;" : "=l"(d) : "l"(a), "l"(b), "l"(c));
    return d;
}
__device__ __forceinline__ u64 dup2(float x) {
    u64 d;
    asm("mov.b64 %0, {%1, %1};" : "=l"(d) : "f"(x));
    return d;
}
__device__ __forceinline__ float2 unpack2(u64 v) {
    float2 r;
    asm("mov.b64 {%0, %1}, %2;" : "=f"(r.x), "=f"(r.y) : "l"(v));
    return r;
}

// ---------------- cp.async helpers -----------------------------------------
__device__ __forceinline__ void cp_async16(uint32_t sa, const void* gp) {
    asm volatile("cp.async.ca.shared.global [%0], [%1], 16;" :: "r"(sa), "l"(gp));
}
__device__ __forceinline__ void cp_commit() {
    asm volatile("cp.async.commit_group;");
}
__device__ __forceinline__ void cp_wait0() {
    asm volatile("cp.async.wait_group 0;");
}

// ---------------- scratch (static device globals; no allocation) ----------
__device__ float g_x   [NP_*BT_*F_];     // x transposed, node-major
__device__ float g_m   [N_*BT_*H_];      // msg / attn scratch
__device__ float g_h0  [NP_*BT_*H_];
__device__ float g_h1  [NP_*BT_*H_];
__device__ float g_qkv [BTN_*3*H_];      // packed q|k|v, row stride 768
__device__ float g_adjp[NP_*NP_];
__device__ float g_wqkv[H_*3*H_];
__device__ float g_bqkv[3*H_];

// ---------------- prep kernels --------------------------------------------
__global__ void adj_prep(const float* __restrict__ adj, float* __restrict__ adjp) {
    int i = blockIdx.x * 256 + threadIdx.x;       // 16384
    int n = i >> 7, m = i & 127;
    adjp[i] = (n < N_ && m < N_) ? adj[n * N_ + m] : 0.f;
}

__global__ void qkv_prep(const float* __restrict__ Wq, const float* __restrict__ Wk,
                         const float* __restrict__ Wv, const float* __restrict__ bq,
                         const float* __restrict__ bk, const float* __restrict__ bv,
                         float* __restrict__ wqkv, float* __restrict__ bqkv) {
    int i = blockIdx.x * 256 + threadIdx.x;       // 196608
    int r = i / (3*H_), c = i % (3*H_);
    int w = c >> 8, cc = c & 255;
    const float* W = (w == 0) ? Wq : (w == 1) ? Wk : Wv;
    wqkv[i] = W[r * H_ + cc];
    if (i < 3*H_) {
        const float* bb = (i < H_) ? bq : (i < 2*H_) ? bk : bv;
        bqkv[i] = bb[i & 255];
    }
}

// x[b,t,n,f] -> g_x[(n*BT + bt)*F + f]
__global__ void xpose_kernel(const float* __restrict__ x, float* __restrict__ xT) {
    int idx = blockIdx.x * 256 + threadIdx.x;
    if (idx >= BTN_ * (F_/4)) return;
    int c   = idx & 15;
    int row = idx >> 4;            // bt*100 + n
    int n   = row % N_;
    int bt  = row / N_;
    ((float4*)xT)[(n * BT_ + bt) * (F_/4) + c] = ((const float4*)x)[idx];
}

// ---------------- double-buffered SGEMM, f32x2 core, cp.async B -----------
// C[M,Nn] = A[M,K] @ B[K,Nn] (+bias)(relu)(+res). 128x128 tile, Kstep 16.
// Thread tile 8(M) x 8(N), N split as cols {tx*4..+3} and {64+tx*4..+3}
// (conflict-free LDS.128 phases). K must be a multiple of 16.
template<bool BIAS, bool RELU, bool RES, bool MG>
__global__ void __launch_bounds__(256, 2) sgemm_kernel(
    const float* __restrict__ A, const float* __restrict__ Bm,
    const float* __restrict__ bias, const float* __restrict__ res,
    float* __restrict__ C, int M, int Nn, int K, int Mvalid) {
    __shared__ __align__(16) float As[2][16][132];
    __shared__ __align__(16) float Bs[2][16][128];

    const int tid = threadIdx.x;
    const int bx = blockIdx.x, by = blockIdx.y;
    const int arow = tid >> 1, acol = (tid & 1) << 3;       // A: 128 rows x 16 k
    const int brow = tid >> 4, bcol = (tid & 15) << 3;      // B: 16 k x 128 cols
    const int tx = tid & 15, ty = tid >> 4;

    const float* Ap = A + ((size_t)by * 128 + arow) * K + acol;
    const float* Bp = Bm + (size_t)brow * Nn + (size_t)bx * 128 + bcol;

    // cp.async destinations for B (two 16B chunks per thread per buffer)
    uint32_t bdst0 = (uint32_t)__cvta_generic_to_shared(&Bs[0][brow][bcol]);
    uint32_t bdst1 = (uint32_t)__cvta_generic_to_shared(&Bs[1][brow][bcol]);

    // packed accumulators: 8 rows x 4 col-pairs
    // j=0,1 -> cols tx*4 + {0,1},{2,3};  j=2,3 -> cols 64+tx*4 + {0,1},{2,3}
    u64 acc[8][4];
#pragma unroll
    for (int i = 0; i < 8; i++)
#pragma unroll
        for (int j = 0; j < 4; j++) acc[i][j] = 0ull;

    // prologue: k-block 0 -> buf 0
    {
        float4 av0 = *(const float4*)(Ap);
        float4 av1 = *(const float4*)(Ap + 4);
        As[0][acol+0][arow] = av0.x;
        As[0][acol+1][arow] = av0.y;
        As[0][acol+2][arow] = av0.z;
        As[0][acol+3][arow] = av0.w;
        As[0][acol+4][arow] = av1.x;
        As[0][acol+5][arow] = av1.y;
        As[0][acol+6][arow] = av1.z;
        As[0][acol+7][arow] = av1.w;
        cp_async16(bdst0,      Bp);
        cp_async16(bdst0 + 16, Bp + 4);
        cp_commit();
        cp_wait0();
    }
    __syncthreads();

    int buf = 0;
    for (int k0 = 16; k0 <= K; k0 += 16) {
        const bool more = (k0 < K);
        float4 av0, av1;
        if (more) {
            av0 = *(const float4*)(Ap + k0);
            av1 = *(const float4*)(Ap + k0 + 4);
            uint32_t bd = buf ? bdst0 : bdst1;   // next buffer
            const float* bsrc = Bp + (size_t)k0 * Nn;
            cp_async16(bd,      bsrc);
            cp_async16(bd + 16, bsrc + 4);
            cp_commit();
        }

        const float (*Asb)[132] = As[buf];
        const float (*Bsb)[128] = Bs[buf];
#pragma unroll
        for (int kk = 0; kk < 16; kk++) {
            float a[8];
            *(float4*)(a)   = *(const float4*)&Asb[kk][ty*8];
            *(float4*)(a+4) = *(const float4*)&Asb[kk][ty*8+4];
            ulonglong2 bp0 = *(const ulonglong2*)&Bsb[kk][tx*4];
            ulonglong2 bp1 = *(const ulonglong2*)&Bsb[kk][64 + tx*4];
            u64 b2[4] = { bp0.x, bp0.y, bp1.x, bp1.y };
#pragma unroll
            for (int i = 0; i < 8; i++) {
                u64 ad = dup2(a[i]);
#pragma unroll
                for (int j = 0; j < 4; j++)
                    acc[i][j] = fma2(ad, b2[j], acc[i][j]);
            }
        }

        if (more) {
            const int nb = buf ^ 1;
            As[nb][acol+0][arow] = av0.x;
            As[nb][acol+1][arow] = av0.y;
            As[nb][acol+2][arow] = av0.z;
            As[nb][acol+3][arow] = av0.w;
            As[nb][acol+4][arow] = av1.x;
            As[nb][acol+5][arow] = av1.y;
            As[nb][acol+6][arow] = av1.z;
            As[nb][acol+7][arow] = av1.w;
            cp_wait0();
            __syncthreads();
            buf = nb;
        }
    }

    // epilogue: two float4 groups per row, cols c0 and c0+64
    const int crow0 = by * 128 + ty * 8;
    const int c0 = bx * 128 + tx * 4;
#pragma unroll
    for (int i = 0; i < 8; i++) {
        if (MG && (crow0 + i) >= Mvalid) continue;
        size_t rbase = (size_t)(crow0 + i) * Nn;
#pragma unroll
        for (int g = 0; g < 2; g++) {
            const int col = c0 + g * 64;
            float2 p0 = unpack2(acc[i][g*2 + 0]);
            float2 p1 = unpack2(acc[i][g*2 + 1]);
            float4 o;
            o.x = p0.x; o.y = p0.y; o.z = p1.x; o.w = p1.y;
            if (BIAS) {
                o.x += bias[col + 0];
                o.y += bias[col + 1];
                o.z += bias[col + 2];
                o.w += bias[col + 3];
            }
            if (RELU) {
                o.x = fmaxf(o.x, 0.f); o.y = fmaxf(o.y, 0.f);
                o.z = fmaxf(o.z, 0.f); o.w = fmaxf(o.w, 0.f);
            }
            if (RES) {
                float4 r = *(const float4*)(res + rbase + col);
                o.x += r.x; o.y += r.y; o.z += r.z; o.w += r.w;
            }
            *(float4*)(C + rbase + col) = o;
        }
    }
}

// ---------------- Temporal attention (packed qkv, node-major) -------------
#define HP_ 260
__global__ void __launch_bounds__(256) attn_kernel(
    const float* __restrict__ qkv, float* __restrict__ out) {
    extern __shared__ float smf[];
    float* q_s = smf;
    float* k_s = smf + T_*HP_;
    float* v_s = smf + 2*T_*HP_;
    float* s_s = smf + 3*T_*HP_;

    const int bn = blockIdx.x;
    const int n = bn >> 6, b = bn & 63;
    const size_t row0 = (size_t)n * BT_ + (size_t)b * T_;
    const int tid = threadIdx.x;

    for (int idx = tid; idx < T_ * 192; idx += 256) {
        int t = idx / 192, c = idx % 192;
        float4 val = ((const float4*)(qkv + (row0 + t) * (3*H_)))[c];
        int which = c >> 6, h4 = c & 63;
        float* dst = (which == 0 ? q_s : which == 1 ? k_s : v_s) + t * HP_ + h4 * 4;
        *(float4*)dst = val;
    }
    __syncthreads();

    for (int p = tid; p < T_*T_; p += 256) {
        int t = p / T_, s = p - t * T_;
        float ax = 0.f, ay = 0.f, az = 0.f, aw = 0.f;
        const float4* qp = (const float4*)(q_s + t * HP_);
        const float4* kp = (const float4*)(k_s + s * HP_);
#pragma unroll 8
        for (int hc = 0; hc < H_/4; hc++) {
            float4 qv = qp[hc];
            float4 kv = kp[hc];
            ax = fmaf(qv.x, kv.x, ax);
            ay = fmaf(qv.y, kv.y, ay);
            az = fmaf(qv.z, kv.z, az);
            aw = fmaf(qv.w, kv.w, aw);
        }
        s_s[t*T_ + s] = (ax + ay + az + aw) * 0.0625f;
    }
    __syncthreads();

    if (tid < T_) {
        float mx = -1e30f;
#pragma unroll
        for (int s = 0; s < T_; s++) mx = fmaxf(mx, s_s[tid*T_+s]);
        float sum = 0.f;
#pragma unroll
        for (int s = 0; s < T_; s++) {
            float e = __expf(s_s[tid*T_+s] - mx);
            s_s[tid*T_+s] = e;
            sum += e;
        }
        float inv = 1.f / sum;
#pragma unroll
        for (int s = 0; s < T_; s++) s_s[tid*T_+s] *= inv;
    }
    __syncthreads();

    for (int idx = tid; idx < T_ * (H_/4); idx += 256) {
        int t = idx >> 6, hc = idx & 63;
        float4 acc = make_float4(0.f, 0.f, 0.f, 0.f);
#pragma unroll
        for (int s = 0; s < T_; s++) {
            float p = s_s[t*T_ + s];
            float4 vv = ((const float4*)(v_s + s * HP_))[hc];
            acc.x = fmaf(p, vv.x, acc.x);
            acc.y = fmaf(p, vv.y, acc.y);
            acc.z = fmaf(p, vv.z, acc.z);
            acc.w = fmaf(p, vv.w, acc.w);
        }
        ((float4*)(out + (row0 + t) * H_))[hc] = acc;
    }
}

// ---------------- LayerNorm + scatter back to [b,t,n,h] -------------------
__inline__ __device__ float warp_sum(float val) {
#pragma unroll
    for (int o = 16; o; o >>= 1) val += __shfl_xor_sync(0xffffffffu, val, o);
    return val;
}

__global__ void __launch_bounds__(256) ln_kernel(
    const float* __restrict__ a, const float* __restrict__ gamma,
    const float* __restrict__ beta, float* __restrict__ out) {
    const int row  = blockIdx.x * 8 + (threadIdx.x >> 5);   // n*BT + bt
    const int lane = threadIdx.x & 31;
    const float4* ap = (const float4*)(a + (size_t)row * H_);
    float4 v0 = ap[lane];
    float4 v1 = ap[lane + 32];

    float s = v0.x + v0.y + v0.z + v0.w + v1.x + v1.y + v1.z + v1.w;
    s = warp_sum(s);
    float mean = s * (1.f / H_);

    float d, sq = 0.f;
    d = v0.x - mean; sq = fmaf(d, d, sq);
    d = v0.y - mean; sq = fmaf(d, d, sq);
    d = v0.z - mean; sq = fmaf(d, d, sq);
    d = v0.w - mean; sq = fmaf(d, d, sq);
    d = v1.x - mean; sq = fmaf(d, d, sq);
    d = v1.y - mean; sq = fmaf(d, d, sq);
    d = v1.z - mean; sq = fmaf(d, d, sq);
    d = v1.w - mean; sq = fmaf(d, d, sq);
    sq = warp_sum(sq);
    float rstd = rsqrtf(sq * (1.f / H_) + LN_EPS);

    float4 g0 = ((const float4*)gamma)[lane];
    float4 g1 = ((const float4*)gamma)[lane + 32];
    float4 be0 = ((const float4*)beta)[lane];
    float4 be1 = ((const float4*)beta)[lane + 32];

    float4 o0, o1;
    o0.x = (v0.x - mean) * rstd * g0.x + be0.x;
    o0.y = (v0.y - mean) * rstd * g0.y + be0.y;
    o0.z = (v0.z - mean) * rstd * g0.z + be0.z;
    o0.w = (v0.w - mean) * rstd * g0.w + be0.w;
    o1.x = (v1.x - mean) * rstd * g1.x + be1.x;
    o1.y = (v1.y - mean) * rstd * g1.y + be1.y;
    o1.z = (v1.z - mean) * rstd * g1.z + be1.z;
    o1.w = (v1.w - mean) * rstd * g1.w + be1.w;

    const int n = row / BT_, bt = row % BT_;
    float4* op = (float4*)(out + ((size_t)bt * N_ + n) * H_);
    op[lane] = o0;
    op[lane + 32] = o1;
}

// ---------------- host launcher -------------------------------------------
extern "C" void kernel_launch(void* const* d_in, const int* in_sizes, int n_in,
                              void* d_out, int out_size) {
    const float* x     = (const float*)d_in[0];
    const float* adj   = (const float*)d_in[1];
    const float* W0    = (const float*)d_in[2];
    const float* b0    = (const float*)d_in[3];
    const float* W1    = (const float*)d_in[4];
    const float* b1    = (const float*)d_in[5];
    const float* W2    = (const float*)d_in[6];
    const float* b2    = (const float*)d_in[7];
    const float* Wq    = (const float*)d_in[8];
    const float* bq    = (const float*)d_in[9];
    const float* Wk    = (const float*)d_in[10];
    const float* bk    = (const float*)d_in[11];
    const float* Wv    = (const float*)d_in[12];
    const float* bv    = (const float*)d_in[13];
    const float* Wp    = (const float*)d_in[14];
    const float* bp    = (const float*)d_in[15];
    const float* gamma = (const float*)d_in[16];
    const float* beta  = (const float*)d_in[17];
    float* outp = (float*)d_out;

    float *xT, *m, *h0, *h1, *qkv, *adjp, *wqkv, *bqkv;
    cudaGetSymbolAddress((void**)&xT,   g_x);
    cudaGetSymbolAddress((void**)&m,    g_m);
    cudaGetSymbolAddress((void**)&h0,   g_h0);
    cudaGetSymbolAddress((void**)&h1,   g_h1);
    cudaGetSymbolAddress((void**)&qkv,  g_qkv);
    cudaGetSymbolAddress((void**)&adjp, g_adjp);
    cudaGetSymbolAddress((void**)&wqkv, g_wqkv);
    cudaGetSymbolAddress((void**)&bqkv, g_bqkv);

    const int attn_smem = (3*T_*HP_ + T_*T_) * sizeof(float);  // 64000 B
    cudaFuncSetAttribute(attn_kernel, cudaFuncAttributeMaxDynamicSharedMemorySize,
                         attn_smem);

    // prep
    adj_prep<<<64, 256>>>(adj, adjp);
    qkv_prep<<<768, 256>>>(Wq, Wk, Wv, bq, bk, bv, wqkv, bqkv);
    xpose_kernel<<<(BTN_*(F_/4) + 255)/256, 256>>>(x, xT);

    // GCN layer 0: msg (K=128 padded, Nn=BT*F) then F->H GEMM + relu
    sgemm_kernel<false,false,false,true><<<dim3(BT_*F_/128, 1), 256>>>(
        adjp, xT, nullptr, nullptr, m, NP_, BT_*F_, NP_, N_);
    sgemm_kernel<true,true,false,false><<<dim3(2, 1000), 256>>>(
        m, W0, b0, nullptr, h0, BTN_, H_, F_, BTN_);

    // GCN layer 1
    sgemm_kernel<false,false,false,true><<<dim3(BT_*H_/128, 1), 256>>>(
        adjp, h0, nullptr, nullptr, m, NP_, BT_*H_, NP_, N_);
    sgemm_kernel<true,true,true,false><<<dim3(2, 1000), 256>>>(
        m, W1, b1, h0, h1, BTN_, H_, H_, BTN_);

    // GCN layer 2
    sgemm_kernel<false,false,false,true><<<dim3(BT_*H_/128, 1), 256>>>(
        adjp, h1, nullptr, nullptr, m, NP_, BT_*H_, NP_, N_);
    sgemm_kernel<true,true,true,false><<<dim3(2, 1000), 256>>>(
        m, W2, b2, h1, h0, BTN_, H_, H_, BTN_);

    // fused QKV projection: [128000 x 256] @ [256 x 768]
    sgemm_kernel<true,false,false,false><<<dim3(6, 1000), 256>>>(
        h0, wqkv, bqkv, nullptr, qkv, BTN_, 3*H_, H_, BTN_);

    // temporal attention -> m
    attn_kernel<<<N_*B_, 256, attn_smem>>>(qkv, m);

    // output projection -> h1
    sgemm_kernel<true,false,false,false><<<dim3(2, 1000), 256>>>(
        m, Wp, bp, nullptr, h1, BTN_, H_, H_, BTN_);

    // layernorm + scatter to [b,t,n,h]
    ln_kernel<<<BTN_/8, 256>>>(h1, gamma, beta, outp);
}